// round 9
// baseline (speedup 1.0000x reference)
#include <cuda_runtime.h>
#include <math.h>
#include <float.h>
#include <stdint.h>

#define BATCH 32
#define NROWS 16384
#define DDIM 64
#define CHUNKS 8
#define RPC (NROWS/CHUNKS)     /* 2048 rows per chunk */
#define TR 128                 /* rows per staged tile */
#define NT (RPC/TR)            /* 16 tiles */
#define TRI 2080
#define TOTAL (BATCH*TRI)      /* 66560 */
#define GRP1 (8*TRI)           /* 16640: run length after round-1 merge */
#define LAMBDA_REG 0.01f
#define SP 72                  /* smem row stride: conflict-free */
#define EPT 16                 /* elems per thread in final merge */

#define COV_SMEM ((2*TR*SP + 16*64) * sizeof(float))   /* 77824 B */
#define MRG_SMEM (GRP1 * sizeof(float))                /* 66560 B */

/* g_Spart: [chunk][batch][3 quadrants][32*32]  (q: 0=Q00, 1=Q11, 2=Q01) */
__device__ float g_Spart[CHUNKS*BATCH*3*1024];
__device__ float g_Csum[CHUNKS*BATCH*DDIM];
__device__ float g_bufA[TOTAL];
__device__ float g_bufB[TOTAL];

__device__ __forceinline__ unsigned tf32r(float v){
    unsigned u;
    asm("cvt.rna.tf32.f32 %0, %1;" : "=r"(u) : "f"(v));
    return u;
}

__device__ __forceinline__ void mma8(float c[4],
                                     unsigned a0, unsigned a1, unsigned a2, unsigned a3,
                                     unsigned b0, unsigned b1){
    asm volatile("mma.sync.aligned.m16n8k8.row.col.f32.tf32.tf32.f32 "
        "{%0,%1,%2,%3},{%4,%5,%6,%7},{%8,%9},{%0,%1,%2,%3};"
        : "+f"(c[0]),"+f"(c[1]),"+f"(c[2]),"+f"(c[3])
        : "r"(a0),"r"(a1),"r"(a2),"r"(a3),"r"(b0),"r"(b1));
}

/* ------------------------------------------------------------------ */
/* Kernel 1: partial Gram via tf32 MMA, symmetric (3 quadrants).      */
/* 128-row tiles, double-buffered, 1 barrier/iter. (measured 35us)    */
/* ------------------------------------------------------------------ */
__global__ __launch_bounds__(256) void cov_partial(const float* __restrict__ x){
    extern __shared__ float dyn[];
    float (*Xs)[TR][SP] = (float (*)[TR][SP])dyn;          /* [2][128][72] */
    float (*red)[64]    = (float (*)[64])(dyn + 2*TR*SP);  /* [16][64]     */

    const int chunk = blockIdx.x;
    const int b     = blockIdx.y;
    const int tid   = threadIdx.x;
    const int wid   = tid >> 5;
    const int lane  = tid & 31;
    const int lg = lane >> 2;
    const int lc = lane & 3;

    int m0, n0, kbase;
    const bool diag = (wid < 4);
    if (wid < 2)      { m0 = 0;  n0 = 0;  kbase = wid * 64;       }
    else if (wid < 4) { m0 = 32; n0 = 32; kbase = (wid - 2) * 64; }
    else              { m0 = 0;  n0 = 32; kbase = (wid - 4) * 32; }

    float acc[2][4][4];
    #pragma unroll
    for (int mt = 0; mt < 2; mt++)
        #pragma unroll
        for (int nt = 0; nt < 4; nt++)
            #pragma unroll
            for (int v = 0; v < 4; v++) acc[mt][nt][v] = 0.f;

    const int sr = tid >> 4;
    const int sc = tid & 15;
    const float* xb = x + ((size_t)b * NROWS + (size_t)chunk * RPC) * DDIM;

    float4 regs[8];
    float cs0 = 0.f, cs1 = 0.f, cs2 = 0.f, cs3 = 0.f;

    {
        #pragma unroll
        for (int i = 0; i < 8; i++)
            regs[i] = *(const float4*)(xb + (size_t)(sr + 16*i)*DDIM + sc*4);
        #pragma unroll
        for (int i = 0; i < 8; i++){
            int row = sr + 16*i;
            cs0 += regs[i].x; cs1 += regs[i].y; cs2 += regs[i].z; cs3 += regs[i].w;
            float4 w;
            w.x = __uint_as_float(tf32r(regs[i].x));
            w.y = __uint_as_float(tf32r(regs[i].y));
            w.z = __uint_as_float(tf32r(regs[i].z));
            w.w = __uint_as_float(tf32r(regs[i].w));
            *(float4*)&Xs[0][row][sc*4] = w;
        }
    }
    __syncthreads();

    for (int t = 0; t < NT; t++){
        const int cb = t & 1;

        if (t + 1 < NT){
            const float* src = xb + (size_t)(t+1) * TR * DDIM;
            #pragma unroll
            for (int i = 0; i < 8; i++)
                regs[i] = *(const float4*)(src + (size_t)(sr + 16*i)*DDIM + sc*4);
        }

        #define DO_STEP(S_)                                                     \
        {                                                                       \
            const int kk = kbase + (S_)*8;                                      \
            unsigned a[2][4];                                                   \
            _Pragma("unroll")                                                   \
            for (int mt = 0; mt < 2; mt++){                                     \
                int m = m0 + mt*16;                                             \
                a[mt][0] = __float_as_uint(Xs[cb][kk   + lc][m     + lg]);      \
                a[mt][1] = __float_as_uint(Xs[cb][kk   + lc][m + 8 + lg]);      \
                a[mt][2] = __float_as_uint(Xs[cb][kk+4 + lc][m     + lg]);      \
                a[mt][3] = __float_as_uint(Xs[cb][kk+4 + lc][m + 8 + lg]);      \
            }                                                                   \
            unsigned bf[4][2];                                                  \
            _Pragma("unroll")                                                   \
            for (int nt = 0; nt < 4; nt++){                                     \
                int nb2 = n0 + nt*8;                                            \
                bf[nt][0] = __float_as_uint(Xs[cb][kk   + lc][nb2 + lg]);       \
                bf[nt][1] = __float_as_uint(Xs[cb][kk+4 + lc][nb2 + lg]);       \
            }                                                                   \
            _Pragma("unroll")                                                   \
            for (int mt = 0; mt < 2; mt++)                                      \
                _Pragma("unroll")                                               \
                for (int nt = 0; nt < 4; nt++)                                  \
                    mma8(acc[mt][nt], a[mt][0], a[mt][1], a[mt][2], a[mt][3],   \
                         bf[nt][0], bf[nt][1]);                                 \
        }

        #define DO_STEP_D(S_)                                                   \
        {                                                                       \
            const int kk = kbase + (S_)*8;                                      \
            unsigned bf[4][2];                                                  \
            _Pragma("unroll")                                                   \
            for (int nt = 0; nt < 4; nt++){                                     \
                int nb2 = n0 + nt*8;                                            \
                bf[nt][0] = __float_as_uint(Xs[cb][kk   + lc][nb2 + lg]);       \
                bf[nt][1] = __float_as_uint(Xs[cb][kk+4 + lc][nb2 + lg]);       \
            }                                                                   \
            _Pragma("unroll")                                                   \
            for (int mt = 0; mt < 2; mt++){                                     \
                unsigned a0 = bf[2*mt][0], a1 = bf[2*mt+1][0];                  \
                unsigned a2 = bf[2*mt][1], a3 = bf[2*mt+1][1];                  \
                _Pragma("unroll")                                               \
                for (int nt = 0; nt < 4; nt++)                                  \
                    mma8(acc[mt][nt], a0, a1, a2, a3, bf[nt][0], bf[nt][1]);    \
            }                                                                   \
        }

        if (diag){
            DO_STEP_D(0) DO_STEP_D(1) DO_STEP_D(2) DO_STEP_D(3)
            DO_STEP_D(4) DO_STEP_D(5) DO_STEP_D(6) DO_STEP_D(7)
        } else {
            DO_STEP(0) DO_STEP(1) DO_STEP(2) DO_STEP(3)
        }
        #undef DO_STEP
        #undef DO_STEP_D

        if (t + 1 < NT){
            const int nb = (t+1) & 1;
            #pragma unroll
            for (int i = 0; i < 8; i++){
                int row = sr + 16*i;
                cs0 += regs[i].x; cs1 += regs[i].y; cs2 += regs[i].z; cs3 += regs[i].w;
                float4 w;
                w.x = __uint_as_float(tf32r(regs[i].x));
                w.y = __uint_as_float(tf32r(regs[i].y));
                w.z = __uint_as_float(tf32r(regs[i].z));
                w.w = __uint_as_float(tf32r(regs[i].w));
                *(float4*)&Xs[nb][row][sc*4] = w;
            }
        }
        __syncthreads();
    }

    red[sr][sc*4+0] = cs0;
    red[sr][sc*4+1] = cs1;
    red[sr][sc*4+2] = cs2;
    red[sr][sc*4+3] = cs3;

    float* sbase = dyn;
    int slot = -1;
    if (wid == 1) slot = 0;
    else if (wid == 3) slot = 1;
    else if (wid >= 5) slot = wid - 3;
    if (slot >= 0){
        float* sc2 = sbase + slot * 1056;
        #pragma unroll
        for (int mt = 0; mt < 2; mt++)
            #pragma unroll
            for (int nt = 0; nt < 4; nt++){
                int rr = mt*16 + lg;
                int cc = nt*8 + lc*2;
                sc2[rr*33 + cc]       = acc[mt][nt][0];
                sc2[rr*33 + cc + 1]   = acc[mt][nt][1];
                sc2[(rr+8)*33 + cc]   = acc[mt][nt][2];
                sc2[(rr+8)*33 + cc+1] = acc[mt][nt][3];
            }
    }
    __syncthreads();

    if (tid < 64){
        float s = 0.f;
        #pragma unroll
        for (int q = 0; q < 16; q++) s += red[q][tid];
        g_Csum[(chunk*BATCH + b)*64 + tid] = s;
    }

    if (wid == 0 || wid == 2 || wid == 4){
        const int q = (wid == 0) ? 0 : (wid == 2) ? 1 : 2;
        const size_t base = ((size_t)(chunk*BATCH + b) * 3 + q) * 1024;
        const float* p0 = sbase + ((wid == 0) ? 0 : (wid == 2) ? 1 : 2) * 1056;
        const float* p1 = (wid == 4) ? sbase + 3*1056 : 0;
        const float* p2 = (wid == 4) ? sbase + 4*1056 : 0;
        #pragma unroll
        for (int mt = 0; mt < 2; mt++)
            #pragma unroll
            for (int nt = 0; nt < 4; nt++){
                int rr = mt*16 + lg;
                int cc = nt*8 + lc*2;
                float v0 = acc[mt][nt][0] + p0[rr*33 + cc];
                float v1 = acc[mt][nt][1] + p0[rr*33 + cc + 1];
                float v2 = acc[mt][nt][2] + p0[(rr+8)*33 + cc];
                float v3 = acc[mt][nt][3] + p0[(rr+8)*33 + cc+1];
                if (wid == 4){
                    v0 += p1[rr*33 + cc]       + p2[rr*33 + cc];
                    v1 += p1[rr*33 + cc + 1]   + p2[rr*33 + cc + 1];
                    v2 += p1[(rr+8)*33 + cc]   + p2[(rr+8)*33 + cc];
                    v3 += p1[(rr+8)*33 + cc+1] + p2[(rr+8)*33 + cc+1];
                }
                g_Spart[base + (size_t)rr*32 + cc]       = v0;
                g_Spart[base + (size_t)rr*32 + cc + 1]   = v1;
                g_Spart[base + (size_t)(rr+8)*32 + cc]   = v2;
                g_Spart[base + (size_t)(rr+8)*32 + cc+1] = v3;
            }
    }
}

/* ------------------------------------------------------------------ */
/* Kernel 2: finalize + hybrid register/smem bitonic sort.            */
/* ------------------------------------------------------------------ */
#define SIDX(i) ((i) + ((i) >> 5))    /* bank-pad swizzle */

__global__ __launch_bounds__(256) void finalize_sort(void){
    __shared__ float mu[64];
    __shared__ float s[4096 + 128];
    const int b = blockIdx.x;
    const int tid = threadIdx.x;

    if (tid < 64){
        float m = 0.f;
        #pragma unroll
        for (int c = 0; c < CHUNKS; c++) m += g_Csum[(c*BATCH + b)*64 + tid];
        mu[tid] = m * (1.f / (float)NROWS);
    }
    __syncthreads();

    for (int t = tid; t < 4096; t += 256){
        float val;
        if (t < TRI){
            int i = (int)((2.f*DDIM + 1.f - sqrtf((2.f*DDIM+1.f)*(2.f*DDIM+1.f) - 8.f*(float)t)) * 0.5f);
            if (i < 0) i = 0;
            if (i > DDIM-1) i = DDIM-1;
            while (i > 0 && (i*DDIM - (i*(i-1))/2) > t) i--;
            while (((i+1)*DDIM - ((i+1)*i)/2) <= t) i++;
            int off = i*DDIM - (i*(i-1))/2;
            int j = i + (t - off);

            int q, r, c2;
            if (j < 32)       { q = 0; r = i;      c2 = j;      }
            else if (i >= 32) { q = 1; r = i - 32; c2 = j - 32; }
            else              { q = 2; r = i;      c2 = j - 32; }

            float acc = 0.f;
            #pragma unroll
            for (int c = 0; c < CHUNKS; c++)
                acc += g_Spart[((size_t)(c*BATCH + b)*3 + q)*1024 + (size_t)r*32 + c2];

            val = (acc - (float)NROWS * mu[i] * mu[j]) * (1.f / (float)(NROWS-1));
            if (i == j) val += LAMBDA_REG;
        } else {
            val = __int_as_float(0x7f800000);  /* +INF pad */
        }
        s[SIDX(t)] = val;
    }
    __syncthreads();

    const int c0 = tid * 16;

    /* stage A: k = 2..16 — fully thread-local */
    {
        float e[16];
        #pragma unroll
        for (int m = 0; m < 16; m++) e[m] = s[SIDX(c0 + m)];
        #pragma unroll
        for (int k = 2; k <= 16; k <<= 1){
            #pragma unroll
            for (int j = k >> 1; j >= 1; j >>= 1){
                #pragma unroll
                for (int m = 0; m < 16; m++){
                    int mm = m ^ j;
                    if (mm > m){
                        bool up = (((c0 + m) & k) == 0);
                        float a = e[m], bb = e[mm];
                        if (up ? (a > bb) : (a < bb)){ e[m] = bb; e[mm] = a; }
                    }
                }
            }
        }
        #pragma unroll
        for (int m = 0; m < 16; m++) s[SIDX(c0 + m)] = e[m];
    }
    __syncthreads();

    /* stage B: k = 32..4096 — smem for j>=16, registers for j<=8 */
    for (int k = 32; k <= 4096; k <<= 1){
        for (int j = k >> 1; j >= 16; j >>= 1){
            #pragma unroll 4
            for (int w = tid; w < 2048; w += 256){
                int i   = ((w & ~(j - 1)) << 1) | (w & (j - 1));
                int ixj = i + j;
                bool up = ((i & k) == 0);
                float a = s[SIDX(i)], bb = s[SIDX(ixj)];
                if (up ? (a > bb) : (a < bb)){ s[SIDX(i)] = bb; s[SIDX(ixj)] = a; }
            }
            __syncthreads();
        }
        {
            float e[16];
            const bool up = ((c0 & k) == 0);
            #pragma unroll
            for (int m = 0; m < 16; m++) e[m] = s[SIDX(c0 + m)];
            #pragma unroll
            for (int j = 8; j >= 1; j >>= 1){
                #pragma unroll
                for (int m = 0; m < 16; m++){
                    int mm = m ^ j;
                    if (mm > m){
                        float a = e[m], bb = e[mm];
                        if (up ? (a > bb) : (a < bb)){ e[m] = bb; e[mm] = a; }
                    }
                }
            }
            #pragma unroll
            for (int m = 0; m < 16; m++) s[SIDX(c0 + m)] = e[m];
        }
        __syncthreads();
    }

    for (int i = tid; i < TRI; i += 256) g_bufA[b*TRI + i] = s[SIDX(i)];
}

/* ------------------------------------------------------------------ */
/* Kernel 3: round-1 merge, 8 runs of 2080 -> 1 run of 16640 (smem).  */
/* ------------------------------------------------------------------ */
__global__ __launch_bounds__(256) void merge8_smem(void){
    extern __shared__ float s[];    /* GRP1 floats */
    const int group = blockIdx.x / 65;
    const int big   = blockIdx.x % 65;
    const int tid   = threadIdx.x;
    const size_t gbase = (size_t)group * GRP1;

    for (int i = tid; i < GRP1; i += 256)
        s[i] = g_bufA[gbase + i];
    __syncthreads();

    const int el    = big*256 + tid;        /* 0..16639 */
    const int r     = el / TRI;
    const int local = el - r*TRI;
    const float v   = s[el];

    int lo[8];
    #pragma unroll
    for (int p = 0; p < 8; p++) lo[p] = 0;

    for (int step = 2048; step >= 1; step >>= 1){
        #pragma unroll
        for (int p = 0; p < 8; p++){
            int probe = lo[p] + step;
            if (p != r && probe <= TRI){
                float w = s[p*TRI + probe - 1];
                bool cc = (p < r) ? (w <= v) : (w < v);
                if (cc) lo[p] = probe;
            }
        }
    }

    int rank = local;
    #pragma unroll
    for (int p = 0; p < 8; p++) rank += lo[p];   /* lo[r] stays 0 */
    g_bufB[gbase + rank] = v;
}

/* ------------------------------------------------------------------ */
/* Kernel 4: round-2 merge, 4 runs of 16640 -> d_out. Merge-path:     */
/* thread owns EPT consecutive elems of one run; ONE partition search */
/* then sequential 4-stream frontier merge (L1-friendly advances).    */
/* ------------------------------------------------------------------ */
__global__ __launch_bounds__(256) void merge4_path(float* __restrict__ out){
    const int t = blockIdx.x * blockDim.x + threadIdx.x;
    const int gid0 = t * EPT;
    if (gid0 >= TOTAL) return;

    const int r      = gid0 / GRP1;
    const int local0 = gid0 - r * GRP1;

    /* preload own EPT elements (independent float4 loads) */
    float v[EPT];
    #pragma unroll
    for (int q = 0; q < EPT/4; q++){
        float4 vv = *(const float4*)&g_bufB[gid0 + q*4];
        v[q*4+0] = vv.x; v[q*4+1] = vv.y; v[q*4+2] = vv.z; v[q*4+3] = vv.w;
    }

    /* partition search for v[0]: 3 interleaved branchless searches */
    int lo[4];
    lo[0] = lo[1] = lo[2] = lo[3] = 0;
    for (int step = 16384; step >= 1; step >>= 1){
        #pragma unroll
        for (int p = 0; p < 4; p++){
            int probe = lo[p] + step;
            if (p != r && probe <= GRP1){
                float w = g_bufB[p*GRP1 + probe - 1];
                bool cc = (p < r) ? (w <= v[0]) : (w < v[0]);
                if (cc) lo[p] = probe;
            }
        }
    }

    /* sequential frontier merge: sibling pointers advance monotonically */
    #pragma unroll
    for (int e = 0; e < EPT; e++){
        float ve = v[e];
        #pragma unroll
        for (int p = 0; p < 4; p++){
            if (p != r){
                int l = lo[p];
                if (p < r){
                    while (l < GRP1 && g_bufB[p*GRP1 + l] <= ve) l++;
                } else {
                    while (l < GRP1 && g_bufB[p*GRP1 + l] <  ve) l++;
                }
                lo[p] = l;
            }
        }
        int rank = local0 + e + lo[0] + lo[1] + lo[2] + lo[3];  /* lo[r]==base? */
        /* note: lo[r] was advanced only if p!=r guard — it stays 0 */
        out[rank] = ve;
    }
}

/* ------------------------------------------------------------------ */
extern "C" void kernel_launch(void* const* d_in, const int* in_sizes, int n_in,
                              void* d_out, int out_size){
    const float* x = (const float*)d_in[0];
    float* out = (float*)d_out;

    cudaFuncSetAttribute(cov_partial,
                         cudaFuncAttributeMaxDynamicSharedMemorySize, COV_SMEM);
    cudaFuncSetAttribute(merge8_smem,
                         cudaFuncAttributeMaxDynamicSharedMemorySize, MRG_SMEM);

    dim3 gcov(CHUNKS, BATCH);
    cov_partial<<<gcov, 256, COV_SMEM>>>(x);
    finalize_sort<<<BATCH, 256>>>();
    merge8_smem<<<260, 256, MRG_SMEM>>>();

    int nthr = TOTAL / EPT;                       /* 4160 */
    merge4_path<<<(nthr + 255) / 256, 256>>>(out);
}

// round 10
// speedup vs baseline: 1.0887x; 1.0887x over previous
#include <cuda_runtime.h>
#include <math.h>
#include <float.h>
#include <stdint.h>

#define BATCH 32
#define NROWS 16384
#define DDIM 64
#define CHUNKS 8
#define RPC (NROWS/CHUNKS)     /* 2048 rows per chunk */
#define TR 128                 /* rows per staged tile */
#define NT (RPC/TR)            /* 16 tiles */
#define TRI 2080
#define TOTAL (BATCH*TRI)      /* 66560 */
#define GRP (16*TRI)           /* 33280: run length after 16-way merge */
#define LAMBDA_REG 0.01f
#define SP 72                  /* smem row stride: conflict-free */

#define COV_SMEM ((2*TR*SP + 16*64) * sizeof(float))   /* 77824 B  */
#define M16_SMEM (GRP * sizeof(float))                 /* 133120 B */

/* g_Spart: [chunk][batch][3 quadrants][32*32]  (q: 0=Q00, 1=Q11, 2=Q01) */
__device__ float g_Spart[CHUNKS*BATCH*3*1024];
__device__ float g_Csum[CHUNKS*BATCH*DDIM];
__device__ float g_bufA[TOTAL];
__device__ float g_bufB[TOTAL];

__device__ __forceinline__ unsigned tf32r(float v){
    unsigned u;
    asm("cvt.rna.tf32.f32 %0, %1;" : "=r"(u) : "f"(v));
    return u;
}

__device__ __forceinline__ void mma8(float c[4],
                                     unsigned a0, unsigned a1, unsigned a2, unsigned a3,
                                     unsigned b0, unsigned b1){
    asm volatile("mma.sync.aligned.m16n8k8.row.col.f32.tf32.tf32.f32 "
        "{%0,%1,%2,%3},{%4,%5,%6,%7},{%8,%9},{%0,%1,%2,%3};"
        : "+f"(c[0]),"+f"(c[1]),"+f"(c[2]),"+f"(c[3])
        : "r"(a0),"r"(a1),"r"(a2),"r"(a3),"r"(b0),"r"(b1));
}

/* ------------------------------------------------------------------ */
/* Kernel 1: partial Gram via tf32 MMA, symmetric (3 quadrants).      */
/* 128-row tiles, double-buffered, 1 barrier/iter. (measured 35us)    */
/* ------------------------------------------------------------------ */
__global__ __launch_bounds__(256) void cov_partial(const float* __restrict__ x){
    extern __shared__ float dyn[];
    float (*Xs)[TR][SP] = (float (*)[TR][SP])dyn;          /* [2][128][72] */
    float (*red)[64]    = (float (*)[64])(dyn + 2*TR*SP);  /* [16][64]     */

    const int chunk = blockIdx.x;
    const int b     = blockIdx.y;
    const int tid   = threadIdx.x;
    const int wid   = tid >> 5;
    const int lane  = tid & 31;
    const int lg = lane >> 2;
    const int lc = lane & 3;

    int m0, n0, kbase;
    const bool diag = (wid < 4);
    if (wid < 2)      { m0 = 0;  n0 = 0;  kbase = wid * 64;       }
    else if (wid < 4) { m0 = 32; n0 = 32; kbase = (wid - 2) * 64; }
    else              { m0 = 0;  n0 = 32; kbase = (wid - 4) * 32; }

    float acc[2][4][4];
    #pragma unroll
    for (int mt = 0; mt < 2; mt++)
        #pragma unroll
        for (int nt = 0; nt < 4; nt++)
            #pragma unroll
            for (int v = 0; v < 4; v++) acc[mt][nt][v] = 0.f;

    const int sr = tid >> 4;
    const int sc = tid & 15;
    const float* xb = x + ((size_t)b * NROWS + (size_t)chunk * RPC) * DDIM;

    float4 regs[8];
    float cs0 = 0.f, cs1 = 0.f, cs2 = 0.f, cs3 = 0.f;

    {
        #pragma unroll
        for (int i = 0; i < 8; i++)
            regs[i] = *(const float4*)(xb + (size_t)(sr + 16*i)*DDIM + sc*4);
        #pragma unroll
        for (int i = 0; i < 8; i++){
            int row = sr + 16*i;
            cs0 += regs[i].x; cs1 += regs[i].y; cs2 += regs[i].z; cs3 += regs[i].w;
            float4 w;
            w.x = __uint_as_float(tf32r(regs[i].x));
            w.y = __uint_as_float(tf32r(regs[i].y));
            w.z = __uint_as_float(tf32r(regs[i].z));
            w.w = __uint_as_float(tf32r(regs[i].w));
            *(float4*)&Xs[0][row][sc*4] = w;
        }
    }
    __syncthreads();

    for (int t = 0; t < NT; t++){
        const int cb = t & 1;

        if (t + 1 < NT){
            const float* src = xb + (size_t)(t+1) * TR * DDIM;
            #pragma unroll
            for (int i = 0; i < 8; i++)
                regs[i] = *(const float4*)(src + (size_t)(sr + 16*i)*DDIM + sc*4);
        }

        #define DO_STEP(S_)                                                     \
        {                                                                       \
            const int kk = kbase + (S_)*8;                                      \
            unsigned a[2][4];                                                   \
            _Pragma("unroll")                                                   \
            for (int mt = 0; mt < 2; mt++){                                     \
                int m = m0 + mt*16;                                             \
                a[mt][0] = __float_as_uint(Xs[cb][kk   + lc][m     + lg]);      \
                a[mt][1] = __float_as_uint(Xs[cb][kk   + lc][m + 8 + lg]);      \
                a[mt][2] = __float_as_uint(Xs[cb][kk+4 + lc][m     + lg]);      \
                a[mt][3] = __float_as_uint(Xs[cb][kk+4 + lc][m + 8 + lg]);      \
            }                                                                   \
            unsigned bf[4][2];                                                  \
            _Pragma("unroll")                                                   \
            for (int nt = 0; nt < 4; nt++){                                     \
                int nb2 = n0 + nt*8;                                            \
                bf[nt][0] = __float_as_uint(Xs[cb][kk   + lc][nb2 + lg]);       \
                bf[nt][1] = __float_as_uint(Xs[cb][kk+4 + lc][nb2 + lg]);       \
            }                                                                   \
            _Pragma("unroll")                                                   \
            for (int mt = 0; mt < 2; mt++)                                      \
                _Pragma("unroll")                                               \
                for (int nt = 0; nt < 4; nt++)                                  \
                    mma8(acc[mt][nt], a[mt][0], a[mt][1], a[mt][2], a[mt][3],   \
                         bf[nt][0], bf[nt][1]);                                 \
        }

        #define DO_STEP_D(S_)                                                   \
        {                                                                       \
            const int kk = kbase + (S_)*8;                                      \
            unsigned bf[4][2];                                                  \
            _Pragma("unroll")                                                   \
            for (int nt = 0; nt < 4; nt++){                                     \
                int nb2 = n0 + nt*8;                                            \
                bf[nt][0] = __float_as_uint(Xs[cb][kk   + lc][nb2 + lg]);       \
                bf[nt][1] = __float_as_uint(Xs[cb][kk+4 + lc][nb2 + lg]);       \
            }                                                                   \
            _Pragma("unroll")                                                   \
            for (int mt = 0; mt < 2; mt++){                                     \
                unsigned a0 = bf[2*mt][0], a1 = bf[2*mt+1][0];                  \
                unsigned a2 = bf[2*mt][1], a3 = bf[2*mt+1][1];                  \
                _Pragma("unroll")                                               \
                for (int nt = 0; nt < 4; nt++)                                  \
                    mma8(acc[mt][nt], a0, a1, a2, a3, bf[nt][0], bf[nt][1]);    \
            }                                                                   \
        }

        if (diag){
            DO_STEP_D(0) DO_STEP_D(1) DO_STEP_D(2) DO_STEP_D(3)
            DO_STEP_D(4) DO_STEP_D(5) DO_STEP_D(6) DO_STEP_D(7)
        } else {
            DO_STEP(0) DO_STEP(1) DO_STEP(2) DO_STEP(3)
        }
        #undef DO_STEP
        #undef DO_STEP_D

        if (t + 1 < NT){
            const int nb = (t+1) & 1;
            #pragma unroll
            for (int i = 0; i < 8; i++){
                int row = sr + 16*i;
                cs0 += regs[i].x; cs1 += regs[i].y; cs2 += regs[i].z; cs3 += regs[i].w;
                float4 w;
                w.x = __uint_as_float(tf32r(regs[i].x));
                w.y = __uint_as_float(tf32r(regs[i].y));
                w.z = __uint_as_float(tf32r(regs[i].z));
                w.w = __uint_as_float(tf32r(regs[i].w));
                *(float4*)&Xs[nb][row][sc*4] = w;
            }
        }
        __syncthreads();
    }

    red[sr][sc*4+0] = cs0;
    red[sr][sc*4+1] = cs1;
    red[sr][sc*4+2] = cs2;
    red[sr][sc*4+3] = cs3;

    float* sbase = dyn;
    int slot = -1;
    if (wid == 1) slot = 0;
    else if (wid == 3) slot = 1;
    else if (wid >= 5) slot = wid - 3;
    if (slot >= 0){
        float* sc2 = sbase + slot * 1056;
        #pragma unroll
        for (int mt = 0; mt < 2; mt++)
            #pragma unroll
            for (int nt = 0; nt < 4; nt++){
                int rr = mt*16 + lg;
                int cc = nt*8 + lc*2;
                sc2[rr*33 + cc]       = acc[mt][nt][0];
                sc2[rr*33 + cc + 1]   = acc[mt][nt][1];
                sc2[(rr+8)*33 + cc]   = acc[mt][nt][2];
                sc2[(rr+8)*33 + cc+1] = acc[mt][nt][3];
            }
    }
    __syncthreads();

    if (tid < 64){
        float s = 0.f;
        #pragma unroll
        for (int q = 0; q < 16; q++) s += red[q][tid];
        g_Csum[(chunk*BATCH + b)*64 + tid] = s;
    }

    if (wid == 0 || wid == 2 || wid == 4){
        const int q = (wid == 0) ? 0 : (wid == 2) ? 1 : 2;
        const size_t base = ((size_t)(chunk*BATCH + b) * 3 + q) * 1024;
        const float* p0 = sbase + ((wid == 0) ? 0 : (wid == 2) ? 1 : 2) * 1056;
        const float* p1 = (wid == 4) ? sbase + 3*1056 : 0;
        const float* p2 = (wid == 4) ? sbase + 4*1056 : 0;
        #pragma unroll
        for (int mt = 0; mt < 2; mt++)
            #pragma unroll
            for (int nt = 0; nt < 4; nt++){
                int rr = mt*16 + lg;
                int cc = nt*8 + lc*2;
                float v0 = acc[mt][nt][0] + p0[rr*33 + cc];
                float v1 = acc[mt][nt][1] + p0[rr*33 + cc + 1];
                float v2 = acc[mt][nt][2] + p0[(rr+8)*33 + cc];
                float v3 = acc[mt][nt][3] + p0[(rr+8)*33 + cc+1];
                if (wid == 4){
                    v0 += p1[rr*33 + cc]       + p2[rr*33 + cc];
                    v1 += p1[rr*33 + cc + 1]   + p2[rr*33 + cc + 1];
                    v2 += p1[(rr+8)*33 + cc]   + p2[(rr+8)*33 + cc];
                    v3 += p1[(rr+8)*33 + cc+1] + p2[(rr+8)*33 + cc+1];
                }
                g_Spart[base + (size_t)rr*32 + cc]       = v0;
                g_Spart[base + (size_t)rr*32 + cc + 1]   = v1;
                g_Spart[base + (size_t)(rr+8)*32 + cc]   = v2;
                g_Spart[base + (size_t)(rr+8)*32 + cc+1] = v3;
            }
    }
}

/* ------------------------------------------------------------------ */
/* Kernel 2: finalize + hybrid register/smem bitonic sort.            */
/* ------------------------------------------------------------------ */
#define SIDX(i) ((i) + ((i) >> 5))    /* bank-pad swizzle */

__global__ __launch_bounds__(256) void finalize_sort(void){
    __shared__ float mu[64];
    __shared__ float s[4096 + 128];
    const int b = blockIdx.x;
    const int tid = threadIdx.x;

    if (tid < 64){
        float m = 0.f;
        #pragma unroll
        for (int c = 0; c < CHUNKS; c++) m += g_Csum[(c*BATCH + b)*64 + tid];
        mu[tid] = m * (1.f / (float)NROWS);
    }
    __syncthreads();

    for (int t = tid; t < 4096; t += 256){
        float val;
        if (t < TRI){
            int i = (int)((2.f*DDIM + 1.f - sqrtf((2.f*DDIM+1.f)*(2.f*DDIM+1.f) - 8.f*(float)t)) * 0.5f);
            if (i < 0) i = 0;
            if (i > DDIM-1) i = DDIM-1;
            while (i > 0 && (i*DDIM - (i*(i-1))/2) > t) i--;
            while (((i+1)*DDIM - ((i+1)*i)/2) <= t) i++;
            int off = i*DDIM - (i*(i-1))/2;
            int j = i + (t - off);

            int q, r, c2;
            if (j < 32)       { q = 0; r = i;      c2 = j;      }
            else if (i >= 32) { q = 1; r = i - 32; c2 = j - 32; }
            else              { q = 2; r = i;      c2 = j - 32; }

            float acc = 0.f;
            #pragma unroll
            for (int c = 0; c < CHUNKS; c++)
                acc += g_Spart[((size_t)(c*BATCH + b)*3 + q)*1024 + (size_t)r*32 + c2];

            val = (acc - (float)NROWS * mu[i] * mu[j]) * (1.f / (float)(NROWS-1));
            if (i == j) val += LAMBDA_REG;
        } else {
            val = __int_as_float(0x7f800000);  /* +INF pad */
        }
        s[SIDX(t)] = val;
    }
    __syncthreads();

    const int c0 = tid * 16;

    /* stage A: k = 2..16 — fully thread-local */
    {
        float e[16];
        #pragma unroll
        for (int m = 0; m < 16; m++) e[m] = s[SIDX(c0 + m)];
        #pragma unroll
        for (int k = 2; k <= 16; k <<= 1){
            #pragma unroll
            for (int j = k >> 1; j >= 1; j >>= 1){
                #pragma unroll
                for (int m = 0; m < 16; m++){
                    int mm = m ^ j;
                    if (mm > m){
                        bool up = (((c0 + m) & k) == 0);
                        float a = e[m], bb = e[mm];
                        if (up ? (a > bb) : (a < bb)){ e[m] = bb; e[mm] = a; }
                    }
                }
            }
        }
        #pragma unroll
        for (int m = 0; m < 16; m++) s[SIDX(c0 + m)] = e[m];
    }
    __syncthreads();

    /* stage B: k = 32..4096 — smem for j>=16, registers for j<=8 */
    for (int k = 32; k <= 4096; k <<= 1){
        for (int j = k >> 1; j >= 16; j >>= 1){
            #pragma unroll 4
            for (int w = tid; w < 2048; w += 256){
                int i   = ((w & ~(j - 1)) << 1) | (w & (j - 1));
                int ixj = i + j;
                bool up = ((i & k) == 0);
                float a = s[SIDX(i)], bb = s[SIDX(ixj)];
                if (up ? (a > bb) : (a < bb)){ s[SIDX(i)] = bb; s[SIDX(ixj)] = a; }
            }
            __syncthreads();
        }
        {
            float e[16];
            const bool up = ((c0 & k) == 0);
            #pragma unroll
            for (int m = 0; m < 16; m++) e[m] = s[SIDX(c0 + m)];
            #pragma unroll
            for (int j = 8; j >= 1; j >>= 1){
                #pragma unroll
                for (int m = 0; m < 16; m++){
                    int mm = m ^ j;
                    if (mm > m){
                        float a = e[m], bb = e[mm];
                        if (up ? (a > bb) : (a < bb)){ e[m] = bb; e[mm] = a; }
                    }
                }
            }
            #pragma unroll
            for (int m = 0; m < 16; m++) s[SIDX(c0 + m)] = e[m];
        }
        __syncthreads();
    }

    for (int i = tid; i < TRI; i += 256) g_bufA[b*TRI + i] = s[SIDX(i)];
}

/* ------------------------------------------------------------------ */
/* Kernel 3: 16-way merge in smem. Block stages 16 runs (133KB) and   */
/* each thread does 15 interleaved branchless binary searches (LDS).  */
/* 32 runs of 2080 -> 2 runs of 33280.                                */
/* ------------------------------------------------------------------ */
#define M16_BLOCKS_PER_GROUP (GRP/256)   /* 130 */

__global__ __launch_bounds__(256) void merge16_smem(void){
    extern __shared__ float s[];    /* GRP floats */
    const int group = blockIdx.x / M16_BLOCKS_PER_GROUP;
    const int big   = blockIdx.x % M16_BLOCKS_PER_GROUP;
    const int tid   = threadIdx.x;
    const size_t gbase = (size_t)group * GRP;

    /* stage 33280 floats via float4 (GRP divisible by 4: 33280/4=8320) */
    {
        const float4* srcv = (const float4*)&g_bufA[gbase];
        float4* dstv = (float4*)s;
        for (int i = tid; i < GRP/4; i += 256)
            dstv[i] = srcv[i];
    }
    __syncthreads();

    const int el    = big*256 + tid;        /* 0..33279 */
    const int r     = el / TRI;
    const int local = el - r*TRI;
    const float v   = s[el];

    int lo[16];
    #pragma unroll
    for (int p = 0; p < 16; p++) lo[p] = 0;

    for (int step = 2048; step >= 1; step >>= 1){
        #pragma unroll
        for (int p = 0; p < 16; p++){
            int probe = lo[p] + step;
            if (p != r && probe <= TRI){
                float w = s[p*TRI + probe - 1];
                bool cc = (p < r) ? (w <= v) : (w < v);
                if (cc) lo[p] = probe;
            }
        }
    }

    int rank = local;
    #pragma unroll
    for (int p = 0; p < 16; p++) rank += lo[p];   /* lo[r] stays 0 */
    g_bufB[gbase + rank] = v;
}

/* ------------------------------------------------------------------ */
/* Kernel 4: final 2-way merge: 2 runs of 33280 -> d_out.             */
/* One 16-step binary search per element (L2-resident sibling run).   */
/* ------------------------------------------------------------------ */
__global__ __launch_bounds__(256) void merge2_final(float* __restrict__ out){
    int gid = blockIdx.x * blockDim.x + threadIdx.x;
    if (gid >= TOTAL) return;

    const int r     = gid / GRP;           /* 0 or 1 */
    const int local = gid - r * GRP;
    const float v   = g_bufB[gid];
    const float* sib = g_bufB + (1 - r) * GRP;
    const bool le = (r == 1);              /* earlier run wins ties */

    int lo = 0;
    for (int step = 32768; step >= 1; step >>= 1){
        int probe = lo + step;
        if (probe <= GRP){
            float w = sib[probe - 1];
            bool cc = le ? (w <= v) : (w < v);
            if (cc) lo = probe;
        }
    }
    out[local + lo] = v;
}

/* ------------------------------------------------------------------ */
extern "C" void kernel_launch(void* const* d_in, const int* in_sizes, int n_in,
                              void* d_out, int out_size){
    const float* x = (const float*)d_in[0];
    float* out = (float*)d_out;

    cudaFuncSetAttribute(cov_partial,
                         cudaFuncAttributeMaxDynamicSharedMemorySize, COV_SMEM);
    cudaFuncSetAttribute(merge16_smem,
                         cudaFuncAttributeMaxDynamicSharedMemorySize, M16_SMEM);

    dim3 gcov(CHUNKS, BATCH);
    cov_partial<<<gcov, 256, COV_SMEM>>>(x);
    finalize_sort<<<BATCH, 256>>>();
    merge16_smem<<<2*M16_BLOCKS_PER_GROUP, 256, M16_SMEM>>>();
    merge2_final<<<(TOTAL + 255) / 256, 256>>>(out);
}

// round 11
// speedup vs baseline: 1.2841x; 1.1794x over previous
#include <cuda_runtime.h>
#include <math.h>
#include <float.h>
#include <stdint.h>

#define BATCH 32
#define NROWS 16384
#define DDIM 64
#define CHUNKS 4
#define RPC (NROWS/CHUNKS)     /* 4096 rows per chunk */
#define TR 128                 /* rows per staged tile */
#define NT (RPC/TR)            /* 32 tiles */
#define TRI 2080
#define TOTAL (BATCH*TRI)      /* 66560 */
#define GRP1 (8*TRI)           /* 16640: run length after round-1 merge */
#define LAMBDA_REG 0.01f
#define SP 72                  /* smem row stride: conflict-free */

#define COV_SMEM ((2*TR*SP + 16*64) * sizeof(float))   /* 77824 B */
#define MRG_SMEM (GRP1 * sizeof(float))                /* 66560 B */

/* g_Spart: [chunk][batch][3 quadrants][32*32]  (q: 0=Q00, 1=Q11, 2=Q01) */
__device__ float g_Spart[CHUNKS*BATCH*3*1024];
__device__ float g_Csum[CHUNKS*BATCH*DDIM];
__device__ float g_bufA[TOTAL];
__device__ float g_bufB[TOTAL];

__device__ __forceinline__ unsigned tf32r(float v){
    unsigned u;
    asm("cvt.rna.tf32.f32 %0, %1;" : "=r"(u) : "f"(v));
    return u;
}

__device__ __forceinline__ void mma8(float c[4],
                                     unsigned a0, unsigned a1, unsigned a2, unsigned a3,
                                     unsigned b0, unsigned b1){
    asm volatile("mma.sync.aligned.m16n8k8.row.col.f32.tf32.tf32.f32 "
        "{%0,%1,%2,%3},{%4,%5,%6,%7},{%8,%9},{%0,%1,%2,%3};"
        : "+f"(c[0]),"+f"(c[1]),"+f"(c[2]),"+f"(c[3])
        : "r"(a0),"r"(a1),"r"(a2),"r"(a3),"r"(b0),"r"(b1));
}

/* ------------------------------------------------------------------ */
/* Kernel 1: partial Gram via tf32 MMA, symmetric (3 quadrants).      */
/* CHUNKS=4 -> grid 128 blocks = exactly ONE balanced wave on 148 SMs.*/
/* 128-row tiles, double-buffered, 1 barrier/iter.                    */
/* ------------------------------------------------------------------ */
__global__ __launch_bounds__(256) void cov_partial(const float* __restrict__ x){
    extern __shared__ float dyn[];
    float (*Xs)[TR][SP] = (float (*)[TR][SP])dyn;          /* [2][128][72] */
    float (*red)[64]    = (float (*)[64])(dyn + 2*TR*SP);  /* [16][64]     */

    const int chunk = blockIdx.x;
    const int b     = blockIdx.y;
    const int tid   = threadIdx.x;
    const int wid   = tid >> 5;
    const int lane  = tid & 31;
    const int lg = lane >> 2;
    const int lc = lane & 3;

    int m0, n0, kbase;
    const bool diag = (wid < 4);
    if (wid < 2)      { m0 = 0;  n0 = 0;  kbase = wid * 64;       }
    else if (wid < 4) { m0 = 32; n0 = 32; kbase = (wid - 2) * 64; }
    else              { m0 = 0;  n0 = 32; kbase = (wid - 4) * 32; }

    float acc[2][4][4];
    #pragma unroll
    for (int mt = 0; mt < 2; mt++)
        #pragma unroll
        for (int nt = 0; nt < 4; nt++)
            #pragma unroll
            for (int v = 0; v < 4; v++) acc[mt][nt][v] = 0.f;

    const int sr = tid >> 4;
    const int sc = tid & 15;
    const float* xb = x + ((size_t)b * NROWS + (size_t)chunk * RPC) * DDIM;

    float4 regs[8];
    float cs0 = 0.f, cs1 = 0.f, cs2 = 0.f, cs3 = 0.f;

    {
        #pragma unroll
        for (int i = 0; i < 8; i++)
            regs[i] = *(const float4*)(xb + (size_t)(sr + 16*i)*DDIM + sc*4);
        #pragma unroll
        for (int i = 0; i < 8; i++){
            int row = sr + 16*i;
            cs0 += regs[i].x; cs1 += regs[i].y; cs2 += regs[i].z; cs3 += regs[i].w;
            float4 w;
            w.x = __uint_as_float(tf32r(regs[i].x));
            w.y = __uint_as_float(tf32r(regs[i].y));
            w.z = __uint_as_float(tf32r(regs[i].z));
            w.w = __uint_as_float(tf32r(regs[i].w));
            *(float4*)&Xs[0][row][sc*4] = w;
        }
    }
    __syncthreads();

    for (int t = 0; t < NT; t++){
        const int cb = t & 1;

        if (t + 1 < NT){
            const float* src = xb + (size_t)(t+1) * TR * DDIM;
            #pragma unroll
            for (int i = 0; i < 8; i++)
                regs[i] = *(const float4*)(src + (size_t)(sr + 16*i)*DDIM + sc*4);
        }

        #define DO_STEP(S_)                                                     \
        {                                                                       \
            const int kk = kbase + (S_)*8;                                      \
            unsigned a[2][4];                                                   \
            _Pragma("unroll")                                                   \
            for (int mt = 0; mt < 2; mt++){                                     \
                int m = m0 + mt*16;                                             \
                a[mt][0] = __float_as_uint(Xs[cb][kk   + lc][m     + lg]);      \
                a[mt][1] = __float_as_uint(Xs[cb][kk   + lc][m + 8 + lg]);      \
                a[mt][2] = __float_as_uint(Xs[cb][kk+4 + lc][m     + lg]);      \
                a[mt][3] = __float_as_uint(Xs[cb][kk+4 + lc][m + 8 + lg]);      \
            }                                                                   \
            unsigned bf[4][2];                                                  \
            _Pragma("unroll")                                                   \
            for (int nt = 0; nt < 4; nt++){                                     \
                int nb2 = n0 + nt*8;                                            \
                bf[nt][0] = __float_as_uint(Xs[cb][kk   + lc][nb2 + lg]);       \
                bf[nt][1] = __float_as_uint(Xs[cb][kk+4 + lc][nb2 + lg]);       \
            }                                                                   \
            _Pragma("unroll")                                                   \
            for (int mt = 0; mt < 2; mt++)                                      \
                _Pragma("unroll")                                               \
                for (int nt = 0; nt < 4; nt++)                                  \
                    mma8(acc[mt][nt], a[mt][0], a[mt][1], a[mt][2], a[mt][3],   \
                         bf[nt][0], bf[nt][1]);                                 \
        }

        #define DO_STEP_D(S_)                                                   \
        {                                                                       \
            const int kk = kbase + (S_)*8;                                      \
            unsigned bf[4][2];                                                  \
            _Pragma("unroll")                                                   \
            for (int nt = 0; nt < 4; nt++){                                     \
                int nb2 = n0 + nt*8;                                            \
                bf[nt][0] = __float_as_uint(Xs[cb][kk   + lc][nb2 + lg]);       \
                bf[nt][1] = __float_as_uint(Xs[cb][kk+4 + lc][nb2 + lg]);       \
            }                                                                   \
            _Pragma("unroll")                                                   \
            for (int mt = 0; mt < 2; mt++){                                     \
                unsigned a0 = bf[2*mt][0], a1 = bf[2*mt+1][0];                  \
                unsigned a2 = bf[2*mt][1], a3 = bf[2*mt+1][1];                  \
                _Pragma("unroll")                                               \
                for (int nt = 0; nt < 4; nt++)                                  \
                    mma8(acc[mt][nt], a0, a1, a2, a3, bf[nt][0], bf[nt][1]);    \
            }                                                                   \
        }

        if (diag){
            DO_STEP_D(0) DO_STEP_D(1) DO_STEP_D(2) DO_STEP_D(3)
            DO_STEP_D(4) DO_STEP_D(5) DO_STEP_D(6) DO_STEP_D(7)
        } else {
            DO_STEP(0) DO_STEP(1) DO_STEP(2) DO_STEP(3)
        }
        #undef DO_STEP
        #undef DO_STEP_D

        if (t + 1 < NT){
            const int nb = (t+1) & 1;
            #pragma unroll
            for (int i = 0; i < 8; i++){
                int row = sr + 16*i;
                cs0 += regs[i].x; cs1 += regs[i].y; cs2 += regs[i].z; cs3 += regs[i].w;
                float4 w;
                w.x = __uint_as_float(tf32r(regs[i].x));
                w.y = __uint_as_float(tf32r(regs[i].y));
                w.z = __uint_as_float(tf32r(regs[i].z));
                w.w = __uint_as_float(tf32r(regs[i].w));
                *(float4*)&Xs[nb][row][sc*4] = w;
            }
        }
        __syncthreads();
    }

    red[sr][sc*4+0] = cs0;
    red[sr][sc*4+1] = cs1;
    red[sr][sc*4+2] = cs2;
    red[sr][sc*4+3] = cs3;

    float* sbase = dyn;
    int slot = -1;
    if (wid == 1) slot = 0;
    else if (wid == 3) slot = 1;
    else if (wid >= 5) slot = wid - 3;
    if (slot >= 0){
        float* sc2 = sbase + slot * 1056;
        #pragma unroll
        for (int mt = 0; mt < 2; mt++)
            #pragma unroll
            for (int nt = 0; nt < 4; nt++){
                int rr = mt*16 + lg;
                int cc = nt*8 + lc*2;
                sc2[rr*33 + cc]       = acc[mt][nt][0];
                sc2[rr*33 + cc + 1]   = acc[mt][nt][1];
                sc2[(rr+8)*33 + cc]   = acc[mt][nt][2];
                sc2[(rr+8)*33 + cc+1] = acc[mt][nt][3];
            }
    }
    __syncthreads();

    if (tid < 64){
        float s = 0.f;
        #pragma unroll
        for (int q = 0; q < 16; q++) s += red[q][tid];
        g_Csum[(chunk*BATCH + b)*64 + tid] = s;
    }

    if (wid == 0 || wid == 2 || wid == 4){
        const int q = (wid == 0) ? 0 : (wid == 2) ? 1 : 2;
        const size_t base = ((size_t)(chunk*BATCH + b) * 3 + q) * 1024;
        const float* p0 = sbase + ((wid == 0) ? 0 : (wid == 2) ? 1 : 2) * 1056;
        const float* p1 = (wid == 4) ? sbase + 3*1056 : 0;
        const float* p2 = (wid == 4) ? sbase + 4*1056 : 0;
        #pragma unroll
        for (int mt = 0; mt < 2; mt++)
            #pragma unroll
            for (int nt = 0; nt < 4; nt++){
                int rr = mt*16 + lg;
                int cc = nt*8 + lc*2;
                float v0 = acc[mt][nt][0] + p0[rr*33 + cc];
                float v1 = acc[mt][nt][1] + p0[rr*33 + cc + 1];
                float v2 = acc[mt][nt][2] + p0[(rr+8)*33 + cc];
                float v3 = acc[mt][nt][3] + p0[(rr+8)*33 + cc+1];
                if (wid == 4){
                    v0 += p1[rr*33 + cc]       + p2[rr*33 + cc];
                    v1 += p1[rr*33 + cc + 1]   + p2[rr*33 + cc + 1];
                    v2 += p1[(rr+8)*33 + cc]   + p2[(rr+8)*33 + cc];
                    v3 += p1[(rr+8)*33 + cc+1] + p2[(rr+8)*33 + cc+1];
                }
                g_Spart[base + (size_t)rr*32 + cc]       = v0;
                g_Spart[base + (size_t)rr*32 + cc + 1]   = v1;
                g_Spart[base + (size_t)(rr+8)*32 + cc]   = v2;
                g_Spart[base + (size_t)(rr+8)*32 + cc+1] = v3;
            }
    }
}

/* ------------------------------------------------------------------ */
/* Kernel 2: finalize + hybrid register/smem bitonic sort.            */
/* ------------------------------------------------------------------ */
#define SIDX(i) ((i) + ((i) >> 5))    /* bank-pad swizzle */

__global__ __launch_bounds__(256) void finalize_sort(void){
    __shared__ float mu[64];
    __shared__ float s[4096 + 128];
    const int b = blockIdx.x;
    const int tid = threadIdx.x;

    if (tid < 64){
        float m = 0.f;
        #pragma unroll
        for (int c = 0; c < CHUNKS; c++) m += g_Csum[(c*BATCH + b)*64 + tid];
        mu[tid] = m * (1.f / (float)NROWS);
    }
    __syncthreads();

    for (int t = tid; t < 4096; t += 256){
        float val;
        if (t < TRI){
            int i = (int)((2.f*DDIM + 1.f - sqrtf((2.f*DDIM+1.f)*(2.f*DDIM+1.f) - 8.f*(float)t)) * 0.5f);
            if (i < 0) i = 0;
            if (i > DDIM-1) i = DDIM-1;
            while (i > 0 && (i*DDIM - (i*(i-1))/2) > t) i--;
            while (((i+1)*DDIM - ((i+1)*i)/2) <= t) i++;
            int off = i*DDIM - (i*(i-1))/2;
            int j = i + (t - off);

            int q, r, c2;
            if (j < 32)       { q = 0; r = i;      c2 = j;      }
            else if (i >= 32) { q = 1; r = i - 32; c2 = j - 32; }
            else              { q = 2; r = i;      c2 = j - 32; }

            float acc = 0.f;
            #pragma unroll
            for (int c = 0; c < CHUNKS; c++)
                acc += g_Spart[((size_t)(c*BATCH + b)*3 + q)*1024 + (size_t)r*32 + c2];

            val = (acc - (float)NROWS * mu[i] * mu[j]) * (1.f / (float)(NROWS-1));
            if (i == j) val += LAMBDA_REG;
        } else {
            val = __int_as_float(0x7f800000);  /* +INF pad */
        }
        s[SIDX(t)] = val;
    }
    __syncthreads();

    const int c0 = tid * 16;

    /* stage A: k = 2..16 — fully thread-local */
    {
        float e[16];
        #pragma unroll
        for (int m = 0; m < 16; m++) e[m] = s[SIDX(c0 + m)];
        #pragma unroll
        for (int k = 2; k <= 16; k <<= 1){
            #pragma unroll
            for (int j = k >> 1; j >= 1; j >>= 1){
                #pragma unroll
                for (int m = 0; m < 16; m++){
                    int mm = m ^ j;
                    if (mm > m){
                        bool up = (((c0 + m) & k) == 0);
                        float a = e[m], bb = e[mm];
                        if (up ? (a > bb) : (a < bb)){ e[m] = bb; e[mm] = a; }
                    }
                }
            }
        }
        #pragma unroll
        for (int m = 0; m < 16; m++) s[SIDX(c0 + m)] = e[m];
    }
    __syncthreads();

    /* stage B: k = 32..4096 — smem for j>=16, registers for j<=8 */
    for (int k = 32; k <= 4096; k <<= 1){
        for (int j = k >> 1; j >= 16; j >>= 1){
            #pragma unroll 4
            for (int w = tid; w < 2048; w += 256){
                int i   = ((w & ~(j - 1)) << 1) | (w & (j - 1));
                int ixj = i + j;
                bool up = ((i & k) == 0);
                float a = s[SIDX(i)], bb = s[SIDX(ixj)];
                if (up ? (a > bb) : (a < bb)){ s[SIDX(i)] = bb; s[SIDX(ixj)] = a; }
            }
            __syncthreads();
        }
        {
            float e[16];
            const bool up = ((c0 & k) == 0);
            #pragma unroll
            for (int m = 0; m < 16; m++) e[m] = s[SIDX(c0 + m)];
            #pragma unroll
            for (int j = 8; j >= 1; j >>= 1){
                #pragma unroll
                for (int m = 0; m < 16; m++){
                    int mm = m ^ j;
                    if (mm > m){
                        float a = e[m], bb = e[mm];
                        if (up ? (a > bb) : (a < bb)){ e[m] = bb; e[mm] = a; }
                    }
                }
            }
            #pragma unroll
            for (int m = 0; m < 16; m++) s[SIDX(c0 + m)] = e[m];
        }
        __syncthreads();
    }

    for (int i = tid; i < TRI; i += 256) g_bufA[b*TRI + i] = s[SIDX(i)];
}

/* ------------------------------------------------------------------ */
/* Kernel 3: round-1 merge, 8 runs of 2080 -> 1 run of 16640 (smem).  */
/* ------------------------------------------------------------------ */
__global__ __launch_bounds__(256) void merge8_smem(void){
    extern __shared__ float s[];    /* GRP1 floats */
    const int group = blockIdx.x / 65;
    const int big   = blockIdx.x % 65;
    const int tid   = threadIdx.x;
    const size_t gbase = (size_t)group * GRP1;

    {
        const float4* srcv = (const float4*)&g_bufA[gbase];
        float4* dstv = (float4*)s;
        for (int i = tid; i < GRP1/4; i += 256)
            dstv[i] = srcv[i];
    }
    __syncthreads();

    const int el    = big*256 + tid;        /* 0..16639 */
    const int r     = el / TRI;
    const int local = el - r*TRI;
    const float v   = s[el];

    int lo[8];
    #pragma unroll
    for (int p = 0; p < 8; p++) lo[p] = 0;

    for (int step = 2048; step >= 1; step >>= 1){
        #pragma unroll
        for (int p = 0; p < 8; p++){
            int probe = lo[p] + step;
            if (p != r && probe <= TRI){
                float w = s[p*TRI + probe - 1];
                bool cc = (p < r) ? (w <= v) : (w < v);
                if (cc) lo[p] = probe;
            }
        }
    }

    int rank = local;
    #pragma unroll
    for (int p = 0; p < 8; p++) rank += lo[p];   /* lo[r] stays 0 */
    g_bufB[gbase + rank] = v;
}

/* ------------------------------------------------------------------ */
/* Kernel 4: final 4-way merge: 4 runs of 16640 -> d_out.             */
/* 3 interleaved branchless binary searches per element (measured     */
/* 11.6us as merge_k<4,14>).                                          */
/* ------------------------------------------------------------------ */
__global__ __launch_bounds__(256) void merge4_final(float* __restrict__ out){
    int gid = blockIdx.x * blockDim.x + threadIdx.x;
    if (gid >= TOTAL) return;

    const int r     = gid / GRP1;
    const int local = gid - r * GRP1;
    const float v   = g_bufB[gid];

    const float* run[3];
    bool useLE[3];
    int lo[3];
    int q = 0;
    #pragma unroll
    for (int sRun = 0; sRun < 4; sRun++){
        if (sRun == r) continue;
        run[q]   = g_bufB + sRun * GRP1;
        useLE[q] = (sRun < r);       /* earlier runs win ties */
        lo[q]    = 0;
        q++;
    }

    for (int step = 16384; step >= 1; step >>= 1){
        #pragma unroll
        for (int p = 0; p < 3; p++){
            int probe = lo[p] + step;
            if (probe <= GRP1){
                float w = run[p][probe - 1];
                bool c = useLE[p] ? (w <= v) : (w < v);
                if (c) lo[p] = probe;
            }
        }
    }

    int rank = local + lo[0] + lo[1] + lo[2];
    out[rank] = v;
}

/* ------------------------------------------------------------------ */
extern "C" void kernel_launch(void* const* d_in, const int* in_sizes, int n_in,
                              void* d_out, int out_size){
    const float* x = (const float*)d_in[0];
    float* out = (float*)d_out;

    cudaFuncSetAttribute(cov_partial,
                         cudaFuncAttributeMaxDynamicSharedMemorySize, COV_SMEM);
    cudaFuncSetAttribute(merge8_smem,
                         cudaFuncAttributeMaxDynamicSharedMemorySize, MRG_SMEM);

    dim3 gcov(CHUNKS, BATCH);
    cov_partial<<<gcov, 256, COV_SMEM>>>(x);
    finalize_sort<<<BATCH, 256>>>();
    merge8_smem<<<260, 256, MRG_SMEM>>>();
    merge4_final<<<(TOTAL + 255) / 256, 256>>>(out);
}

// round 12
// speedup vs baseline: 1.5094x; 1.1755x over previous
#include <cuda_runtime.h>
#include <math.h>
#include <float.h>
#include <stdint.h>

#define BATCH 32
#define NROWS 16384
#define DDIM 64
#define CHUNKS 8
#define RPC (NROWS/CHUNKS)     /* 2048 rows per chunk */
#define TR 128                 /* rows per staged tile */
#define NT (RPC/TR)            /* 16 tiles */
#define TRI 2080
#define TOTAL (BATCH*TRI)      /* 66560 */
#define GRP1 (8*TRI)           /* 16640: run length after round-1 merge */
#define LAMBDA_REG 0.01f
#define SP 72                  /* smem row stride: conflict-free */

#define COV_SMEM ((2*TR*SP + 16*64) * sizeof(float))   /* 77824 B */
#define MRG_SMEM (GRP1 * sizeof(float))                /* 66560 B */

/* g_Spart: [chunk][batch][3 quadrants][32*32]  (q: 0=Q00, 1=Q11, 2=Q01) */
__device__ float g_Spart[CHUNKS*BATCH*3*1024];
__device__ float g_Csum[CHUNKS*BATCH*DDIM];
__device__ float g_bufA[TOTAL];
__device__ float g_bufB[TOTAL];

__device__ __forceinline__ unsigned tf32r(float v){
    unsigned u;
    asm("cvt.rna.tf32.f32 %0, %1;" : "=r"(u) : "f"(v));
    return u;
}

__device__ __forceinline__ void mma8(float c[4],
                                     unsigned a0, unsigned a1, unsigned a2, unsigned a3,
                                     unsigned b0, unsigned b1){
    asm volatile("mma.sync.aligned.m16n8k8.row.col.f32.tf32.tf32.f32 "
        "{%0,%1,%2,%3},{%4,%5,%6,%7},{%8,%9},{%0,%1,%2,%3};"
        : "+f"(c[0]),"+f"(c[1]),"+f"(c[2]),"+f"(c[3])
        : "r"(a0),"r"(a1),"r"(a2),"r"(a3),"r"(b0),"r"(b1));
}

/* ------------------------------------------------------------------ */
/* Kernel 1: partial Gram via tf32 MMA, symmetric (3 quadrants).      */
/* CHUNKS=8 -> 256 blocks -> 2 blocks/SM (mutual latency hiding).     */
/* 128-row tiles, double-buffered, 1 barrier/iter. Measured 35.3us.   */
/* ------------------------------------------------------------------ */
__global__ __launch_bounds__(256) void cov_partial(const float* __restrict__ x){
    extern __shared__ float dyn[];
    float (*Xs)[TR][SP] = (float (*)[TR][SP])dyn;          /* [2][128][72] */
    float (*red)[64]    = (float (*)[64])(dyn + 2*TR*SP);  /* [16][64]     */

    const int chunk = blockIdx.x;
    const int b     = blockIdx.y;
    const int tid   = threadIdx.x;
    const int wid   = tid >> 5;
    const int lane  = tid & 31;
    const int lg = lane >> 2;
    const int lc = lane & 3;

    int m0, n0, kbase;
    const bool diag = (wid < 4);
    if (wid < 2)      { m0 = 0;  n0 = 0;  kbase = wid * 64;       }
    else if (wid < 4) { m0 = 32; n0 = 32; kbase = (wid - 2) * 64; }
    else              { m0 = 0;  n0 = 32; kbase = (wid - 4) * 32; }

    float acc[2][4][4];
    #pragma unroll
    for (int mt = 0; mt < 2; mt++)
        #pragma unroll
        for (int nt = 0; nt < 4; nt++)
            #pragma unroll
            for (int v = 0; v < 4; v++) acc[mt][nt][v] = 0.f;

    const int sr = tid >> 4;
    const int sc = tid & 15;
    const float* xb = x + ((size_t)b * NROWS + (size_t)chunk * RPC) * DDIM;

    float4 regs[8];
    float cs0 = 0.f, cs1 = 0.f, cs2 = 0.f, cs3 = 0.f;

    {
        #pragma unroll
        for (int i = 0; i < 8; i++)
            regs[i] = *(const float4*)(xb + (size_t)(sr + 16*i)*DDIM + sc*4);
        #pragma unroll
        for (int i = 0; i < 8; i++){
            int row = sr + 16*i;
            cs0 += regs[i].x; cs1 += regs[i].y; cs2 += regs[i].z; cs3 += regs[i].w;
            float4 w;
            w.x = __uint_as_float(tf32r(regs[i].x));
            w.y = __uint_as_float(tf32r(regs[i].y));
            w.z = __uint_as_float(tf32r(regs[i].z));
            w.w = __uint_as_float(tf32r(regs[i].w));
            *(float4*)&Xs[0][row][sc*4] = w;
        }
    }
    __syncthreads();

    for (int t = 0; t < NT; t++){
        const int cb = t & 1;

        if (t + 1 < NT){
            const float* src = xb + (size_t)(t+1) * TR * DDIM;
            #pragma unroll
            for (int i = 0; i < 8; i++)
                regs[i] = *(const float4*)(src + (size_t)(sr + 16*i)*DDIM + sc*4);
        }

        #define DO_STEP(S_)                                                     \
        {                                                                       \
            const int kk = kbase + (S_)*8;                                      \
            unsigned a[2][4];                                                   \
            _Pragma("unroll")                                                   \
            for (int mt = 0; mt < 2; mt++){                                     \
                int m = m0 + mt*16;                                             \
                a[mt][0] = __float_as_uint(Xs[cb][kk   + lc][m     + lg]);      \
                a[mt][1] = __float_as_uint(Xs[cb][kk   + lc][m + 8 + lg]);      \
                a[mt][2] = __float_as_uint(Xs[cb][kk+4 + lc][m     + lg]);      \
                a[mt][3] = __float_as_uint(Xs[cb][kk+4 + lc][m + 8 + lg]);      \
            }                                                                   \
            unsigned bf[4][2];                                                  \
            _Pragma("unroll")                                                   \
            for (int nt = 0; nt < 4; nt++){                                     \
                int nb2 = n0 + nt*8;                                            \
                bf[nt][0] = __float_as_uint(Xs[cb][kk   + lc][nb2 + lg]);       \
                bf[nt][1] = __float_as_uint(Xs[cb][kk+4 + lc][nb2 + lg]);       \
            }                                                                   \
            _Pragma("unroll")                                                   \
            for (int mt = 0; mt < 2; mt++)                                      \
                _Pragma("unroll")                                               \
                for (int nt = 0; nt < 4; nt++)                                  \
                    mma8(acc[mt][nt], a[mt][0], a[mt][1], a[mt][2], a[mt][3],   \
                         bf[nt][0], bf[nt][1]);                                 \
        }

        #define DO_STEP_D(S_)                                                   \
        {                                                                       \
            const int kk = kbase + (S_)*8;                                      \
            unsigned bf[4][2];                                                  \
            _Pragma("unroll")                                                   \
            for (int nt = 0; nt < 4; nt++){                                     \
                int nb2 = n0 + nt*8;                                            \
                bf[nt][0] = __float_as_uint(Xs[cb][kk   + lc][nb2 + lg]);       \
                bf[nt][1] = __float_as_uint(Xs[cb][kk+4 + lc][nb2 + lg]);       \
            }                                                                   \
            _Pragma("unroll")                                                   \
            for (int mt = 0; mt < 2; mt++){                                     \
                unsigned a0 = bf[2*mt][0], a1 = bf[2*mt+1][0];                  \
                unsigned a2 = bf[2*mt][1], a3 = bf[2*mt+1][1];                  \
                _Pragma("unroll")                                               \
                for (int nt = 0; nt < 4; nt++)                                  \
                    mma8(acc[mt][nt], a0, a1, a2, a3, bf[nt][0], bf[nt][1]);    \
            }                                                                   \
        }

        if (diag){
            DO_STEP_D(0) DO_STEP_D(1) DO_STEP_D(2) DO_STEP_D(3)
            DO_STEP_D(4) DO_STEP_D(5) DO_STEP_D(6) DO_STEP_D(7)
        } else {
            DO_STEP(0) DO_STEP(1) DO_STEP(2) DO_STEP(3)
        }
        #undef DO_STEP
        #undef DO_STEP_D

        if (t + 1 < NT){
            const int nb = (t+1) & 1;
            #pragma unroll
            for (int i = 0; i < 8; i++){
                int row = sr + 16*i;
                cs0 += regs[i].x; cs1 += regs[i].y; cs2 += regs[i].z; cs3 += regs[i].w;
                float4 w;
                w.x = __uint_as_float(tf32r(regs[i].x));
                w.y = __uint_as_float(tf32r(regs[i].y));
                w.z = __uint_as_float(tf32r(regs[i].z));
                w.w = __uint_as_float(tf32r(regs[i].w));
                *(float4*)&Xs[nb][row][sc*4] = w;
            }
        }
        __syncthreads();
    }

    red[sr][sc*4+0] = cs0;
    red[sr][sc*4+1] = cs1;
    red[sr][sc*4+2] = cs2;
    red[sr][sc*4+3] = cs3;

    float* sbase = dyn;
    int slot = -1;
    if (wid == 1) slot = 0;
    else if (wid == 3) slot = 1;
    else if (wid >= 5) slot = wid - 3;
    if (slot >= 0){
        float* sc2 = sbase + slot * 1056;
        #pragma unroll
        for (int mt = 0; mt < 2; mt++)
            #pragma unroll
            for (int nt = 0; nt < 4; nt++){
                int rr = mt*16 + lg;
                int cc = nt*8 + lc*2;
                sc2[rr*33 + cc]       = acc[mt][nt][0];
                sc2[rr*33 + cc + 1]   = acc[mt][nt][1];
                sc2[(rr+8)*33 + cc]   = acc[mt][nt][2];
                sc2[(rr+8)*33 + cc+1] = acc[mt][nt][3];
            }
    }
    __syncthreads();

    if (tid < 64){
        float s = 0.f;
        #pragma unroll
        for (int q = 0; q < 16; q++) s += red[q][tid];
        g_Csum[(chunk*BATCH + b)*64 + tid] = s;
    }

    if (wid == 0 || wid == 2 || wid == 4){
        const int q = (wid == 0) ? 0 : (wid == 2) ? 1 : 2;
        const size_t base = ((size_t)(chunk*BATCH + b) * 3 + q) * 1024;
        const float* p0 = sbase + ((wid == 0) ? 0 : (wid == 2) ? 1 : 2) * 1056;
        const float* p1 = (wid == 4) ? sbase + 3*1056 : 0;
        const float* p2 = (wid == 4) ? sbase + 4*1056 : 0;
        #pragma unroll
        for (int mt = 0; mt < 2; mt++)
            #pragma unroll
            for (int nt = 0; nt < 4; nt++){
                int rr = mt*16 + lg;
                int cc = nt*8 + lc*2;
                float v0 = acc[mt][nt][0] + p0[rr*33 + cc];
                float v1 = acc[mt][nt][1] + p0[rr*33 + cc + 1];
                float v2 = acc[mt][nt][2] + p0[(rr+8)*33 + cc];
                float v3 = acc[mt][nt][3] + p0[(rr+8)*33 + cc+1];
                if (wid == 4){
                    v0 += p1[rr*33 + cc]       + p2[rr*33 + cc];
                    v1 += p1[rr*33 + cc + 1]   + p2[rr*33 + cc + 1];
                    v2 += p1[(rr+8)*33 + cc]   + p2[(rr+8)*33 + cc];
                    v3 += p1[(rr+8)*33 + cc+1] + p2[(rr+8)*33 + cc+1];
                }
                g_Spart[base + (size_t)rr*32 + cc]       = v0;
                g_Spart[base + (size_t)rr*32 + cc + 1]   = v1;
                g_Spart[base + (size_t)(rr+8)*32 + cc]   = v2;
                g_Spart[base + (size_t)(rr+8)*32 + cc+1] = v3;
            }
    }
}

/* ------------------------------------------------------------------ */
/* Kernel 2: finalize + hybrid bitonic, 512 threads x 8 elems.        */
/* Thread-local j<=4, smem j>=8 (45 phases over 16 warps).            */
/* ------------------------------------------------------------------ */
#define SIDX(i) ((i) + ((i) >> 5))    /* bank-pad swizzle */

__global__ __launch_bounds__(512) void finalize_sort(void){
    __shared__ float mu[64];
    __shared__ float s[4096 + 128];
    const int b = blockIdx.x;
    const int tid = threadIdx.x;

    if (tid < 64){
        float m = 0.f;
        #pragma unroll
        for (int c = 0; c < CHUNKS; c++) m += g_Csum[(c*BATCH + b)*64 + tid];
        mu[tid] = m * (1.f / (float)NROWS);
    }
    __syncthreads();

    for (int t = tid; t < 4096; t += 512){
        float val;
        if (t < TRI){
            int i = (int)((2.f*DDIM + 1.f - sqrtf((2.f*DDIM+1.f)*(2.f*DDIM+1.f) - 8.f*(float)t)) * 0.5f);
            if (i < 0) i = 0;
            if (i > DDIM-1) i = DDIM-1;
            while (i > 0 && (i*DDIM - (i*(i-1))/2) > t) i--;
            while (((i+1)*DDIM - ((i+1)*i)/2) <= t) i++;
            int off = i*DDIM - (i*(i-1))/2;
            int j = i + (t - off);

            int q, r, c2;
            if (j < 32)       { q = 0; r = i;      c2 = j;      }
            else if (i >= 32) { q = 1; r = i - 32; c2 = j - 32; }
            else              { q = 2; r = i;      c2 = j - 32; }

            float acc = 0.f;
            #pragma unroll
            for (int c = 0; c < CHUNKS; c++)
                acc += g_Spart[((size_t)(c*BATCH + b)*3 + q)*1024 + (size_t)r*32 + c2];

            val = (acc - (float)NROWS * mu[i] * mu[j]) * (1.f / (float)(NROWS-1));
            if (i == j) val += LAMBDA_REG;
        } else {
            val = __int_as_float(0x7f800000);  /* +INF pad */
        }
        s[SIDX(t)] = val;
    }
    __syncthreads();

    const int c0 = tid * 8;

    /* stage A: k = 2..8 — fully thread-local */
    {
        float e[8];
        #pragma unroll
        for (int m = 0; m < 8; m++) e[m] = s[SIDX(c0 + m)];
        #pragma unroll
        for (int k = 2; k <= 8; k <<= 1){
            #pragma unroll
            for (int j = k >> 1; j >= 1; j >>= 1){
                #pragma unroll
                for (int m = 0; m < 8; m++){
                    int mm = m ^ j;
                    if (mm > m){
                        bool up = (((c0 + m) & k) == 0);
                        float a = e[m], bb = e[mm];
                        if (up ? (a > bb) : (a < bb)){ e[m] = bb; e[mm] = a; }
                    }
                }
            }
        }
        #pragma unroll
        for (int m = 0; m < 8; m++) s[SIDX(c0 + m)] = e[m];
    }
    __syncthreads();

    /* stage B: k = 16..4096 — smem for j>=8, registers for j<=4 */
    for (int k = 16; k <= 4096; k <<= 1){
        for (int j = k >> 1; j >= 8; j >>= 1){
            #pragma unroll 2
            for (int w = tid; w < 2048; w += 512){
                int i   = ((w & ~(j - 1)) << 1) | (w & (j - 1));
                int ixj = i + j;
                bool up = ((i & k) == 0);
                float a = s[SIDX(i)], bb = s[SIDX(ixj)];
                if (up ? (a > bb) : (a < bb)){ s[SIDX(i)] = bb; s[SIDX(ixj)] = a; }
            }
            __syncthreads();
        }
        {
            float e[8];
            const bool up = ((c0 & k) == 0);
            #pragma unroll
            for (int m = 0; m < 8; m++) e[m] = s[SIDX(c0 + m)];
            #pragma unroll
            for (int j = 4; j >= 1; j >>= 1){
                #pragma unroll
                for (int m = 0; m < 8; m++){
                    int mm = m ^ j;
                    if (mm > m){
                        float a = e[m], bb = e[mm];
                        if (up ? (a > bb) : (a < bb)){ e[m] = bb; e[mm] = a; }
                    }
                }
            }
            #pragma unroll
            for (int m = 0; m < 8; m++) s[SIDX(c0 + m)] = e[m];
        }
        __syncthreads();
    }

    for (int i = tid; i < TRI; i += 512) g_bufA[b*TRI + i] = s[SIDX(i)];
}

/* ------------------------------------------------------------------ */
/* Kernel 3: round-1 merge, 8 runs of 2080 -> 1 run of 16640 (smem).  */
/* 512 outputs per block (halved staging traffic vs 256).             */
/* ------------------------------------------------------------------ */
#define M8_BPG ((GRP1 + 511)/512)   /* 33 blocks per group */

__global__ __launch_bounds__(512) void merge8_smem(void){
    extern __shared__ float s[];    /* GRP1 floats */
    const int group = blockIdx.x / M8_BPG;
    const int big   = blockIdx.x % M8_BPG;
    const int tid   = threadIdx.x;
    const size_t gbase = (size_t)group * GRP1;

    {
        const float4* srcv = (const float4*)&g_bufA[gbase];
        float4* dstv = (float4*)s;
        for (int i = tid; i < GRP1/4; i += 512)
            dstv[i] = srcv[i];
    }
    __syncthreads();

    const int el = big*512 + tid;           /* 0..16895, guard below */
    if (el >= GRP1) return;
    const int r     = el / TRI;
    const int local = el - r*TRI;
    const float v   = s[el];

    int lo[8];
    #pragma unroll
    for (int p = 0; p < 8; p++) lo[p] = 0;

    for (int step = 2048; step >= 1; step >>= 1){
        #pragma unroll
        for (int p = 0; p < 8; p++){
            int probe = lo[p] + step;
            if (p != r && probe <= TRI){
                float w = s[p*TRI + probe - 1];
                bool cc = (p < r) ? (w <= v) : (w < v);
                if (cc) lo[p] = probe;
            }
        }
    }

    int rank = local;
    #pragma unroll
    for (int p = 0; p < 8; p++) rank += lo[p];   /* lo[r] stays 0 */
    g_bufB[gbase + rank] = v;
}

/* ------------------------------------------------------------------ */
/* Kernel 4: final 4-way merge: 4 runs of 16640 -> d_out.             */
/* 3 interleaved branchless binary searches (measured 10.5us).        */
/* ------------------------------------------------------------------ */
__global__ __launch_bounds__(256) void merge4_final(float* __restrict__ out){
    int gid = blockIdx.x * blockDim.x + threadIdx.x;
    if (gid >= TOTAL) return;

    const int r     = gid / GRP1;
    const int local = gid - r * GRP1;
    const float v   = g_bufB[gid];

    const float* run[3];
    bool useLE[3];
    int lo[3];
    int q = 0;
    #pragma unroll
    for (int sRun = 0; sRun < 4; sRun++){
        if (sRun == r) continue;
        run[q]   = g_bufB + sRun * GRP1;
        useLE[q] = (sRun < r);       /* earlier runs win ties */
        lo[q]    = 0;
        q++;
    }

    for (int step = 16384; step >= 1; step >>= 1){
        #pragma unroll
        for (int p = 0; p < 3; p++){
            int probe = lo[p] + step;
            if (probe <= GRP1){
                float w = run[p][probe - 1];
                bool c = useLE[p] ? (w <= v) : (w < v);
                if (c) lo[p] = probe;
            }
        }
    }

    int rank = local + lo[0] + lo[1] + lo[2];
    out[rank] = v;
}

/* ------------------------------------------------------------------ */
extern "C" void kernel_launch(void* const* d_in, const int* in_sizes, int n_in,
                              void* d_out, int out_size){
    const float* x = (const float*)d_in[0];
    float* out = (float*)d_out;

    cudaFuncSetAttribute(cov_partial,
                         cudaFuncAttributeMaxDynamicSharedMemorySize, COV_SMEM);
    cudaFuncSetAttribute(merge8_smem,
                         cudaFuncAttributeMaxDynamicSharedMemorySize, MRG_SMEM);

    dim3 gcov(CHUNKS, BATCH);
    cov_partial<<<gcov, 256, COV_SMEM>>>(x);
    finalize_sort<<<BATCH, 512>>>();
    merge8_smem<<<4*M8_BPG, 512, MRG_SMEM>>>();
    merge4_final<<<(TOTAL + 255) / 256, 256>>>(out);
}